// round 9
// baseline (speedup 1.0000x reference)
#include <cuda_runtime.h>
#include <cuda_fp16.h>

#define NNODES 50000
#define NEDGES 1600000
#define DIM 64
#define CAP 128        // per-node edge bin capacity (deg~Poisson(32))
#define BN 64          // nodes per block in node_kernel

// Scratch (allocation-free rule: __device__ globals)
__device__ uint2  d_g2h[NNODES * 16];       // per-node message, fp16x4 per entry [N,64]
__device__ float  d_hsum[NNODES * DIM];     // h_x + h_mu  [N,64]
__device__ float  d_v[3 * DIM];             // v1 | v2 | v3
__device__ float  d_Sw[NNODES];             // scalar segment sum of edge_w
__device__ int    d_cnt[NNODES];            // per-node edge cursor/degree
__device__ int    d_rec[NNODES * CAP];      // dst index per (src, slot)
__device__ float  d_W3t[DIM * DIM];         // W3 transposed:  [k][o]
__device__ float  d_W4ct[DIM * DIM];        // W4c transposed: [k][o]

__device__ __forceinline__ void fma4(float4& c, float s, float4 w) {
    c.x += s * w.x; c.y += s * w.y; c.z += s * w.z; c.w += s * w.w;
}

// ---------------------------------------------------------------------------
// Kernel Z: zero cursors/Sw before the (concurrent) placement pass.
// ---------------------------------------------------------------------------
__global__ void zero_kernel() {
    int t = blockIdx.x * 256 + threadIdx.x;
    if (t < NNODES) { d_cnt[t] = 0; d_Sw[t] = 0.f; }
}

// ---------------------------------------------------------------------------
// Kernel A: v-vectors + weight transposes (one-time, tiny).
//   v1 = W4a*relu(W1), v2 = W4a*relu(-W1), v3 = W4b*relu(W2)
//   d_W3t[k][o] = W3[o][k],  d_W4ct[k][o] = W4[o][128+k]
// ---------------------------------------------------------------------------
__global__ __launch_bounds__(256) void prep_v_kernel(
    const float* __restrict__ W1, const float* __restrict__ W2,
    const float* __restrict__ W3, const float* __restrict__ W4) {
    int tid = threadIdx.x;
    if (tid < DIM) {
        int o = tid;
        float a = 0.f, b = 0.f, c = 0.f;
#pragma unroll
        for (int j = 0; j < DIM; j++) {
            float w4a = W4[o * 192 + j];
            float w4b = W4[o * 192 + 64 + j];
            float w1 = W1[j], w2 = W2[j];
            a += w4a * fmaxf(w1, 0.f);
            b += w4a * fmaxf(-w1, 0.f);
            c += w4b * fmaxf(w2, 0.f);
        }
        d_v[o] = a;
        d_v[64 + o] = b;
        d_v[128 + o] = c;
    }
    for (int i = tid; i < DIM * DIM; i += 256) {
        int k = i >> 6, o = i & 63;
        d_W3t[k * DIM + o]  = W3[o * DIM + k];
        d_W4ct[k * DIM + o] = W4[o * 192 + 128 + k];
    }
}

// ---------------------------------------------------------------------------
// Kernel B: register-blocked fused node GEMMs.
// 64 nodes x 64 feats per block; 16x16 thread grid, 4x4 tile per thread.
// Phase 1: hs = relu(mu @ W3t);  Phase 2: g = hs @ W4ct; fused epilogue.
// Per k-quad: 8 LDS.128 + 64 FFMA, 16 independent accumulator chains.
// ---------------------------------------------------------------------------
__global__ __launch_bounds__(256) void node_kernel(
    const float* __restrict__ mu, const float* __restrict__ x,
    const float* __restrict__ W1) {
    __shared__ float Ws[DIM * DIM];    // current weight tile, k-major
    __shared__ float mus[BN * DIM];    // staged mu rows
    __shared__ float hs[BN * DIM];     // phase-1 output / phase-2 input
    __shared__ float xs[BN];

    int tid = threadIdx.x;
    int node0 = blockIdx.x * BN;

    // stage mu (row-clamped for the tail block), W3t, x
    for (int i = tid; i < BN * DIM / 4; i += 256) {
        int row = i >> 4, col = i & 15;
        int gr = node0 + row; if (gr > NNODES - 1) gr = NNODES - 1;
        ((float4*)mus)[i] = ((const float4*)(mu + gr * DIM))[col];
    }
    for (int i = tid; i < DIM * DIM / 4; i += 256)
        ((float4*)Ws)[i] = ((const float4*)d_W3t)[i];
    if (tid < BN) {
        int gr = node0 + tid; if (gr > NNODES - 1) gr = NNODES - 1;
        xs[tid] = x[gr];
    }
    __syncthreads();

    int tx = tid & 15, ty = tid >> 4;
    int f0 = tx * 4, n0 = ty * 4;

    float4 a0, a1, a2, a3;
    float4 c0, c1, c2, c3;
    c0 = c1 = c2 = c3 = make_float4(0.f, 0.f, 0.f, 0.f);

    // Phase 1: h = mu @ W3t
#pragma unroll 4
    for (int k4 = 0; k4 < 16; k4++) {
        int kb = k4 * 4;
        float4 w0 = *(const float4*)&Ws[(kb + 0) * DIM + f0];
        float4 w1 = *(const float4*)&Ws[(kb + 1) * DIM + f0];
        float4 w2 = *(const float4*)&Ws[(kb + 2) * DIM + f0];
        float4 w3 = *(const float4*)&Ws[(kb + 3) * DIM + f0];
        a0 = *(const float4*)&mus[(n0 + 0) * DIM + kb];
        a1 = *(const float4*)&mus[(n0 + 1) * DIM + kb];
        a2 = *(const float4*)&mus[(n0 + 2) * DIM + kb];
        a3 = *(const float4*)&mus[(n0 + 3) * DIM + kb];
        fma4(c0, a0.x, w0); fma4(c0, a0.y, w1); fma4(c0, a0.z, w2); fma4(c0, a0.w, w3);
        fma4(c1, a1.x, w0); fma4(c1, a1.y, w1); fma4(c1, a1.z, w2); fma4(c1, a1.w, w3);
        fma4(c2, a2.x, w0); fma4(c2, a2.y, w1); fma4(c2, a2.z, w2); fma4(c2, a2.w, w3);
        fma4(c3, a3.x, w0); fma4(c3, a3.y, w1); fma4(c3, a3.z, w2); fma4(c3, a3.w, w3);
    }
    // relu -> hs
    {
        float4 r;
        r.x = fmaxf(c0.x, 0.f); r.y = fmaxf(c0.y, 0.f); r.z = fmaxf(c0.z, 0.f); r.w = fmaxf(c0.w, 0.f);
        *(float4*)&hs[(n0 + 0) * DIM + f0] = r;
        r.x = fmaxf(c1.x, 0.f); r.y = fmaxf(c1.y, 0.f); r.z = fmaxf(c1.z, 0.f); r.w = fmaxf(c1.w, 0.f);
        *(float4*)&hs[(n0 + 1) * DIM + f0] = r;
        r.x = fmaxf(c2.x, 0.f); r.y = fmaxf(c2.y, 0.f); r.z = fmaxf(c2.z, 0.f); r.w = fmaxf(c2.w, 0.f);
        *(float4*)&hs[(n0 + 2) * DIM + f0] = r;
        r.x = fmaxf(c3.x, 0.f); r.y = fmaxf(c3.y, 0.f); r.z = fmaxf(c3.z, 0.f); r.w = fmaxf(c3.w, 0.f);
        *(float4*)&hs[(n0 + 3) * DIM + f0] = r;
    }
    __syncthreads();

    // swap weights to W4ct
    for (int i = tid; i < DIM * DIM / 4; i += 256)
        ((float4*)Ws)[i] = ((const float4*)d_W4ct)[i];
    __syncthreads();

    // Phase 2: g = hs @ W4ct
    c0 = c1 = c2 = c3 = make_float4(0.f, 0.f, 0.f, 0.f);
#pragma unroll 4
    for (int k4 = 0; k4 < 16; k4++) {
        int kb = k4 * 4;
        float4 w0 = *(const float4*)&Ws[(kb + 0) * DIM + f0];
        float4 w1 = *(const float4*)&Ws[(kb + 1) * DIM + f0];
        float4 w2 = *(const float4*)&Ws[(kb + 2) * DIM + f0];
        float4 w3 = *(const float4*)&Ws[(kb + 3) * DIM + f0];
        a0 = *(const float4*)&hs[(n0 + 0) * DIM + kb];
        a1 = *(const float4*)&hs[(n0 + 1) * DIM + kb];
        a2 = *(const float4*)&hs[(n0 + 2) * DIM + kb];
        a3 = *(const float4*)&hs[(n0 + 3) * DIM + kb];
        fma4(c0, a0.x, w0); fma4(c0, a0.y, w1); fma4(c0, a0.z, w2); fma4(c0, a0.w, w3);
        fma4(c1, a1.x, w0); fma4(c1, a1.y, w1); fma4(c1, a1.z, w2); fma4(c1, a1.w, w3);
        fma4(c2, a2.x, w0); fma4(c2, a2.y, w1); fma4(c2, a2.z, w2); fma4(c2, a2.w, w3);
        fma4(c3, a3.x, w0); fma4(c3, a3.y, w1); fma4(c3, a3.z, w2); fma4(c3, a3.w, w3);
    }

    // epilogue: hsum = hx + h ; g2 = g + xp*v1 + xn*v2 (fp16)
    float4 w1v = *(const float4*)(W1 + f0);
    float4 v1v = *(const float4*)(d_v + f0);
    float4 v2v = *(const float4*)(d_v + 64 + f0);
    float4 rw1, rw1n;
    rw1.x = fmaxf(w1v.x, 0.f); rw1.y = fmaxf(w1v.y, 0.f); rw1.z = fmaxf(w1v.z, 0.f); rw1.w = fmaxf(w1v.w, 0.f);
    rw1n.x = fmaxf(-w1v.x, 0.f); rw1n.y = fmaxf(-w1v.y, 0.f); rw1n.z = fmaxf(-w1v.z, 0.f); rw1n.w = fmaxf(-w1v.w, 0.f);

#pragma unroll
    for (int j = 0; j < 4; j++) {
        int n = node0 + n0 + j;
        if (n >= NNODES) break;
        float4 g = (j == 0) ? c0 : (j == 1) ? c1 : (j == 2) ? c2 : c3;
        float4 h = *(const float4*)&hs[(n0 + j) * DIM + f0];
        float xv = xs[n0 + j];
        float xp = fmaxf(xv, 0.f), xn = fmaxf(-xv, 0.f);

        float4 hsum;
        hsum.x = xp * rw1.x + xn * rw1n.x + h.x;
        hsum.y = xp * rw1.y + xn * rw1n.y + h.y;
        hsum.z = xp * rw1.z + xn * rw1n.z + h.z;
        hsum.w = xp * rw1.w + xn * rw1n.w + h.w;
        *(float4*)&d_hsum[n * DIM + f0] = hsum;

        float4 g2;
        g2.x = g.x + xp * v1v.x + xn * v2v.x;
        g2.y = g.y + xp * v1v.y + xn * v2v.y;
        g2.z = g.z + xp * v1v.z + xn * v2v.z;
        g2.w = g.w + xp * v1v.w + xn * v2v.w;
        __half2 lo = __floats2half2_rn(g2.x, g2.y);
        __half2 hi = __floats2half2_rn(g2.z, g2.w);
        uint2 pk;
        pk.x = *(const unsigned int*)&lo;
        pk.y = *(const unsigned int*)&hi;
        d_g2h[n * 16 + (f0 >> 2)] = pk;
    }
}

// ---------------------------------------------------------------------------
// Kernel C: bucket edges by src (proven form). Runs concurrently with
// node_kernel on a side stream (disjoint scratch, disjoint HW resources).
// ---------------------------------------------------------------------------
__global__ __launch_bounds__(256) void place_kernel(
    const int* __restrict__ ei, const float* __restrict__ ew) {
    int e = blockIdx.x * blockDim.x + threadIdx.x;
    if (e >= NEDGES) return;
    int s = ei[e];            // scatter segment
    int d = ei[NEDGES + e];   // gather node
    int slot = atomicAdd(&d_cnt[s], 1);
    if (slot < CAP) d_rec[s * CAP + slot] = d;
    atomicAdd(&d_Sw[s], ew[e]);
}

// ---------------------------------------------------------------------------
// Kernel D: pull-based segment sum + fused finalize (proven form).
// 16 threads per node; fp16x4 (8B) gathers, fp32 accumulation, no atomics.
//   out = relu(hsum + relu(acc + Sw*v3))
// ---------------------------------------------------------------------------
__global__ __launch_bounds__(256) void agg_final_kernel(float* __restrict__ out) {
    int n = blockIdx.x * 16 + (threadIdx.x >> 4);
    int q = threadIdx.x & 15;

    int deg = min(d_cnt[n], CAP);
    const int* recs = d_rec + n * CAP;

    float4 acc = make_float4(0.f, 0.f, 0.f, 0.f);

    int i = 0;
    for (; i + 4 <= deg; i += 4) {
        int r0 = recs[i], r1 = recs[i + 1], r2 = recs[i + 2], r3 = recs[i + 3];
        uint2 u0 = d_g2h[r0 * 16 + q];
        uint2 u1 = d_g2h[r1 * 16 + q];
        uint2 u2 = d_g2h[r2 * 16 + q];
        uint2 u3 = d_g2h[r3 * 16 + q];
        float2 a0 = __half22float2(*(const __half2*)&u0.x);
        float2 b0 = __half22float2(*(const __half2*)&u0.y);
        float2 a1 = __half22float2(*(const __half2*)&u1.x);
        float2 b1 = __half22float2(*(const __half2*)&u1.y);
        float2 a2 = __half22float2(*(const __half2*)&u2.x);
        float2 b2 = __half22float2(*(const __half2*)&u2.y);
        float2 a3 = __half22float2(*(const __half2*)&u3.x);
        float2 b3 = __half22float2(*(const __half2*)&u3.y);
        acc.x += (a0.x + a1.x) + (a2.x + a3.x);
        acc.y += (a0.y + a1.y) + (a2.y + a3.y);
        acc.z += (b0.x + b1.x) + (b2.x + b3.x);
        acc.w += (b0.y + b1.y) + (b2.y + b3.y);
    }
    for (; i < deg; i++) {
        uint2 u0 = d_g2h[recs[i] * 16 + q];
        float2 a0 = __half22float2(*(const __half2*)&u0.x);
        float2 b0 = __half22float2(*(const __half2*)&u0.y);
        acc.x += a0.x; acc.y += a0.y; acc.z += b0.x; acc.w += b0.y;
    }

    float sw = d_Sw[n];
    float4 v3 = ((const float4*)(d_v + 128))[q];
    float4 hsv = ((const float4*)d_hsum)[n * 16 + q];
    float4 o4;
    o4.x = fmaxf(hsv.x + fmaxf(acc.x + sw * v3.x, 0.f), 0.f);
    o4.y = fmaxf(hsv.y + fmaxf(acc.y + sw * v3.y, 0.f), 0.f);
    o4.z = fmaxf(hsv.z + fmaxf(acc.z + sw * v3.z, 0.f), 0.f);
    o4.w = fmaxf(hsv.w + fmaxf(acc.w + sw * v3.w, 0.f), 0.f);
    ((float4*)out)[n * 16 + q] = o4;
}

// ---------------------------------------------------------------------------
// Fork-join: zero -> [ place (side stream) || prep -> node (main) ] -> agg.
// ---------------------------------------------------------------------------
extern "C" void kernel_launch(void* const* d_in, const int* in_sizes, int n_in,
                              void* d_out, int out_size) {
    const float* mu = (const float*)d_in[0];
    const float* x  = (const float*)d_in[1];
    const int*   ei = (const int*)d_in[2];
    const float* ew = (const float*)d_in[3];
    const float* W1 = (const float*)d_in[4];
    const float* W2 = (const float*)d_in[5];
    const float* W3 = (const float*)d_in[6];
    const float* W4 = (const float*)d_in[7];

    static cudaStream_t s_side = nullptr;
    static cudaEvent_t ev_fork, ev_join;
    if (!s_side) {
        cudaStreamCreateWithFlags(&s_side, cudaStreamNonBlocking);
        cudaEventCreateWithFlags(&ev_fork, cudaEventDisableTiming);
        cudaEventCreateWithFlags(&ev_join, cudaEventDisableTiming);
    }

    zero_kernel<<<(NNODES + 255) / 256, 256>>>();
    cudaEventRecord(ev_fork, 0);
    cudaStreamWaitEvent(s_side, ev_fork, 0);

    place_kernel<<<(NEDGES + 255) / 256, 256, 0, s_side>>>(ei, ew);

    prep_v_kernel<<<1, 256>>>(W1, W2, W3, W4);
    node_kernel<<<(NNODES + BN - 1) / BN, 256>>>(mu, x, W1);

    cudaEventRecord(ev_join, s_side);
    cudaStreamWaitEvent(0, ev_join, 0);

    agg_final_kernel<<<(NNODES + 15) / 16, 256>>>((float*)d_out);
}

// round 10
// speedup vs baseline: 1.7729x; 1.7729x over previous
#include <cuda_runtime.h>
#include <cuda_fp16.h>

#define NNODES 50000
#define NEDGES 1600000
#define DIM 64
#define CAP 128        // per-node edge bin capacity (deg~Poisson(32))
#define BN 64          // nodes per block in node_kernel

// Scratch (allocation-free rule: __device__ globals)
__device__ uint2  d_g2h[NNODES * 16];       // per-node message, fp16x4 per entry [N,64]
__device__ float  d_hsum[NNODES * DIM];     // h_x + h_mu  [N,64]
__device__ float  d_v[3 * DIM];             // v1 | v2 | v3
__device__ unsigned long long d_cw[NNODES]; // packed: cnt<<40 | fixedpoint(Sw)
__device__ int    d_rec[NNODES * CAP];      // dst index per (src, slot)
__device__ float  d_W3t[DIM * DIM];         // W3 transposed:  [k][o]
__device__ float  d_W4ct[DIM * DIM];        // W4c transposed: [k][o]

#define FIXSCALE 1048576.0f   // 2^20 fixed-point for edge weights

__device__ __forceinline__ void fma4(float4& c, float s, float4 w) {
    c.x += s * w.x; c.y += s * w.y; c.z += s * w.z; c.w += s * w.w;
}

// ---------------------------------------------------------------------------
// Kernel Z: zero packed cursors before the (concurrent) placement pass.
// ---------------------------------------------------------------------------
__global__ void zero_kernel() {
    int t = blockIdx.x * 256 + threadIdx.x;
    if (t < NNODES) d_cw[t] = 0ULL;
}

// ---------------------------------------------------------------------------
// Kernel A: v-vectors + weight transposes (one-time, tiny).
//   v1 = W4a*relu(W1), v2 = W4a*relu(-W1), v3 = W4b*relu(W2)
//   d_W3t[k][o] = W3[o][k],  d_W4ct[k][o] = W4[o][128+k]
// ---------------------------------------------------------------------------
__global__ __launch_bounds__(256) void prep_v_kernel(
    const float* __restrict__ W1, const float* __restrict__ W2,
    const float* __restrict__ W3, const float* __restrict__ W4) {
    int tid = threadIdx.x;
    if (tid < DIM) {
        int o = tid;
        float a = 0.f, b = 0.f, c = 0.f;
#pragma unroll
        for (int j = 0; j < DIM; j++) {
            float w4a = W4[o * 192 + j];
            float w4b = W4[o * 192 + 64 + j];
            float w1 = W1[j], w2 = W2[j];
            a += w4a * fmaxf(w1, 0.f);
            b += w4a * fmaxf(-w1, 0.f);
            c += w4b * fmaxf(w2, 0.f);
        }
        d_v[o] = a;
        d_v[64 + o] = b;
        d_v[128 + o] = c;
    }
    for (int i = tid; i < DIM * DIM; i += 256) {
        int k = i >> 6, o = i & 63;
        d_W3t[k * DIM + o]  = W3[o * DIM + k];
        d_W4ct[k * DIM + o] = W4[o * 192 + 128 + k];
    }
}

// ---------------------------------------------------------------------------
// Kernel B: register-blocked fused node GEMMs (R9-proven, 53.7us).
// 64 nodes x 64 feats per block; 16x16 thread grid, 4x4 tile per thread.
// ---------------------------------------------------------------------------
__global__ __launch_bounds__(256) void node_kernel(
    const float* __restrict__ mu, const float* __restrict__ x,
    const float* __restrict__ W1) {
    __shared__ float Ws[DIM * DIM];    // current weight tile, k-major
    __shared__ float mus[BN * DIM];    // staged mu rows
    __shared__ float hs[BN * DIM];     // phase-1 output / phase-2 input
    __shared__ float xs[BN];

    int tid = threadIdx.x;
    int node0 = blockIdx.x * BN;

    for (int i = tid; i < BN * DIM / 4; i += 256) {
        int row = i >> 4, col = i & 15;
        int gr = node0 + row; if (gr > NNODES - 1) gr = NNODES - 1;
        ((float4*)mus)[i] = ((const float4*)(mu + gr * DIM))[col];
    }
    for (int i = tid; i < DIM * DIM / 4; i += 256)
        ((float4*)Ws)[i] = ((const float4*)d_W3t)[i];
    if (tid < BN) {
        int gr = node0 + tid; if (gr > NNODES - 1) gr = NNODES - 1;
        xs[tid] = x[gr];
    }
    __syncthreads();

    int tx = tid & 15, ty = tid >> 4;
    int f0 = tx * 4, n0 = ty * 4;

    float4 a0, a1, a2, a3;
    float4 c0, c1, c2, c3;
    c0 = c1 = c2 = c3 = make_float4(0.f, 0.f, 0.f, 0.f);

    // Phase 1: h = mu @ W3t
#pragma unroll 4
    for (int k4 = 0; k4 < 16; k4++) {
        int kb = k4 * 4;
        float4 w0 = *(const float4*)&Ws[(kb + 0) * DIM + f0];
        float4 w1 = *(const float4*)&Ws[(kb + 1) * DIM + f0];
        float4 w2 = *(const float4*)&Ws[(kb + 2) * DIM + f0];
        float4 w3 = *(const float4*)&Ws[(kb + 3) * DIM + f0];
        a0 = *(const float4*)&mus[(n0 + 0) * DIM + kb];
        a1 = *(const float4*)&mus[(n0 + 1) * DIM + kb];
        a2 = *(const float4*)&mus[(n0 + 2) * DIM + kb];
        a3 = *(const float4*)&mus[(n0 + 3) * DIM + kb];
        fma4(c0, a0.x, w0); fma4(c0, a0.y, w1); fma4(c0, a0.z, w2); fma4(c0, a0.w, w3);
        fma4(c1, a1.x, w0); fma4(c1, a1.y, w1); fma4(c1, a1.z, w2); fma4(c1, a1.w, w3);
        fma4(c2, a2.x, w0); fma4(c2, a2.y, w1); fma4(c2, a2.z, w2); fma4(c2, a2.w, w3);
        fma4(c3, a3.x, w0); fma4(c3, a3.y, w1); fma4(c3, a3.z, w2); fma4(c3, a3.w, w3);
    }
    {
        float4 r;
        r.x = fmaxf(c0.x, 0.f); r.y = fmaxf(c0.y, 0.f); r.z = fmaxf(c0.z, 0.f); r.w = fmaxf(c0.w, 0.f);
        *(float4*)&hs[(n0 + 0) * DIM + f0] = r;
        r.x = fmaxf(c1.x, 0.f); r.y = fmaxf(c1.y, 0.f); r.z = fmaxf(c1.z, 0.f); r.w = fmaxf(c1.w, 0.f);
        *(float4*)&hs[(n0 + 1) * DIM + f0] = r;
        r.x = fmaxf(c2.x, 0.f); r.y = fmaxf(c2.y, 0.f); r.z = fmaxf(c2.z, 0.f); r.w = fmaxf(c2.w, 0.f);
        *(float4*)&hs[(n0 + 2) * DIM + f0] = r;
        r.x = fmaxf(c3.x, 0.f); r.y = fmaxf(c3.y, 0.f); r.z = fmaxf(c3.z, 0.f); r.w = fmaxf(c3.w, 0.f);
        *(float4*)&hs[(n0 + 3) * DIM + f0] = r;
    }
    __syncthreads();

    for (int i = tid; i < DIM * DIM / 4; i += 256)
        ((float4*)Ws)[i] = ((const float4*)d_W4ct)[i];
    __syncthreads();

    // Phase 2: g = hs @ W4ct
    c0 = c1 = c2 = c3 = make_float4(0.f, 0.f, 0.f, 0.f);
#pragma unroll 4
    for (int k4 = 0; k4 < 16; k4++) {
        int kb = k4 * 4;
        float4 w0 = *(const float4*)&Ws[(kb + 0) * DIM + f0];
        float4 w1 = *(const float4*)&Ws[(kb + 1) * DIM + f0];
        float4 w2 = *(const float4*)&Ws[(kb + 2) * DIM + f0];
        float4 w3 = *(const float4*)&Ws[(kb + 3) * DIM + f0];
        a0 = *(const float4*)&hs[(n0 + 0) * DIM + kb];
        a1 = *(const float4*)&hs[(n0 + 1) * DIM + kb];
        a2 = *(const float4*)&hs[(n0 + 2) * DIM + kb];
        a3 = *(const float4*)&hs[(n0 + 3) * DIM + kb];
        fma4(c0, a0.x, w0); fma4(c0, a0.y, w1); fma4(c0, a0.z, w2); fma4(c0, a0.w, w3);
        fma4(c1, a1.x, w0); fma4(c1, a1.y, w1); fma4(c1, a1.z, w2); fma4(c1, a1.w, w3);
        fma4(c2, a2.x, w0); fma4(c2, a2.y, w1); fma4(c2, a2.z, w2); fma4(c2, a2.w, w3);
        fma4(c3, a3.x, w0); fma4(c3, a3.y, w1); fma4(c3, a3.z, w2); fma4(c3, a3.w, w3);
    }

    float4 w1v = *(const float4*)(W1 + f0);
    float4 v1v = *(const float4*)(d_v + f0);
    float4 v2v = *(const float4*)(d_v + 64 + f0);
    float4 rw1, rw1n;
    rw1.x = fmaxf(w1v.x, 0.f); rw1.y = fmaxf(w1v.y, 0.f); rw1.z = fmaxf(w1v.z, 0.f); rw1.w = fmaxf(w1v.w, 0.f);
    rw1n.x = fmaxf(-w1v.x, 0.f); rw1n.y = fmaxf(-w1v.y, 0.f); rw1n.z = fmaxf(-w1v.z, 0.f); rw1n.w = fmaxf(-w1v.w, 0.f);

#pragma unroll
    for (int j = 0; j < 4; j++) {
        int n = node0 + n0 + j;
        if (n >= NNODES) break;
        float4 g = (j == 0) ? c0 : (j == 1) ? c1 : (j == 2) ? c2 : c3;
        float4 h = *(const float4*)&hs[(n0 + j) * DIM + f0];
        float xv = xs[n0 + j];
        float xp = fmaxf(xv, 0.f), xn = fmaxf(-xv, 0.f);

        float4 hsum;
        hsum.x = xp * rw1.x + xn * rw1n.x + h.x;
        hsum.y = xp * rw1.y + xn * rw1n.y + h.y;
        hsum.z = xp * rw1.z + xn * rw1n.z + h.z;
        hsum.w = xp * rw1.w + xn * rw1n.w + h.w;
        *(float4*)&d_hsum[n * DIM + f0] = hsum;

        float4 g2;
        g2.x = g.x + xp * v1v.x + xn * v2v.x;
        g2.y = g.y + xp * v1v.y + xn * v2v.y;
        g2.z = g.z + xp * v1v.z + xn * v2v.z;
        g2.w = g.w + xp * v1v.w + xn * v2v.w;
        __half2 lo = __floats2half2_rn(g2.x, g2.y);
        __half2 hi = __floats2half2_rn(g2.z, g2.w);
        uint2 pk;
        pk.x = *(const unsigned int*)&lo;
        pk.y = *(const unsigned int*)&hi;
        d_g2h[n * 16 + (f0 >> 2)] = pk;
    }
}

// ---------------------------------------------------------------------------
// Kernel C: bucket edges by src. ONE 64-bit returning atomic per edge:
// packed (cnt += 1<<40) | (Sw += round(w * 2^20)). Halves place's atomic ops.
// Max Sw bits: 128 * 2^20 < 2^27 << 2^40 -> no carry into cnt field.
// ---------------------------------------------------------------------------
__global__ __launch_bounds__(256) void place_kernel(
    const int* __restrict__ ei, const float* __restrict__ ew) {
    int e = blockIdx.x * blockDim.x + threadIdx.x;
    if (e >= NEDGES) return;
    int s = ei[e];            // scatter segment
    int d = ei[NEDGES + e];   // gather node
    unsigned int wq = __float2uint_rn(ew[e] * FIXSCALE);
    unsigned long long pk = (1ULL << 40) | (unsigned long long)wq;
    unsigned long long old = atomicAdd(&d_cw[s], pk);
    int slot = (int)(old >> 40);
    if (slot < CAP) d_rec[s * CAP + slot] = d;
}

// ---------------------------------------------------------------------------
// Kernel D: pull-based segment sum + fused finalize (proven form).
// 16 threads per node; fp16x4 (8B) gathers, fp32 accumulation, no atomics.
//   out = relu(hsum + relu(acc + Sw*v3))
// ---------------------------------------------------------------------------
__global__ __launch_bounds__(256) void agg_final_kernel(float* __restrict__ out) {
    int n = blockIdx.x * 16 + (threadIdx.x >> 4);
    int q = threadIdx.x & 15;

    unsigned long long cw = d_cw[n];
    int deg = min((int)(cw >> 40), CAP);
    float sw = (float)(cw & 0xFFFFFFFFFFULL) * (1.0f / FIXSCALE);
    const int* recs = d_rec + n * CAP;

    float4 acc = make_float4(0.f, 0.f, 0.f, 0.f);

    int i = 0;
    for (; i + 4 <= deg; i += 4) {
        int r0 = recs[i], r1 = recs[i + 1], r2 = recs[i + 2], r3 = recs[i + 3];
        uint2 u0 = d_g2h[r0 * 16 + q];
        uint2 u1 = d_g2h[r1 * 16 + q];
        uint2 u2 = d_g2h[r2 * 16 + q];
        uint2 u3 = d_g2h[r3 * 16 + q];
        float2 a0 = __half22float2(*(const __half2*)&u0.x);
        float2 b0 = __half22float2(*(const __half2*)&u0.y);
        float2 a1 = __half22float2(*(const __half2*)&u1.x);
        float2 b1 = __half22float2(*(const __half2*)&u1.y);
        float2 a2 = __half22float2(*(const __half2*)&u2.x);
        float2 b2 = __half22float2(*(const __half2*)&u2.y);
        float2 a3 = __half22float2(*(const __half2*)&u3.x);
        float2 b3 = __half22float2(*(const __half2*)&u3.y);
        acc.x += (a0.x + a1.x) + (a2.x + a3.x);
        acc.y += (a0.y + a1.y) + (a2.y + a3.y);
        acc.z += (b0.x + b1.x) + (b2.x + b3.x);
        acc.w += (b0.y + b1.y) + (b2.y + b3.y);
    }
    for (; i < deg; i++) {
        uint2 u0 = d_g2h[recs[i] * 16 + q];
        float2 a0 = __half22float2(*(const __half2*)&u0.x);
        float2 b0 = __half22float2(*(const __half2*)&u0.y);
        acc.x += a0.x; acc.y += a0.y; acc.z += b0.x; acc.w += b0.y;
    }

    float4 v3 = ((const float4*)(d_v + 128))[q];
    float4 hsv = ((const float4*)d_hsum)[n * 16 + q];
    float4 o4;
    o4.x = fmaxf(hsv.x + fmaxf(acc.x + sw * v3.x, 0.f), 0.f);
    o4.y = fmaxf(hsv.y + fmaxf(acc.y + sw * v3.y, 0.f), 0.f);
    o4.z = fmaxf(hsv.z + fmaxf(acc.z + sw * v3.z, 0.f), 0.f);
    o4.w = fmaxf(hsv.w + fmaxf(acc.w + sw * v3.w, 0.f), 0.f);
    ((float4*)out)[n * 16 + q] = o4;
}

// ---------------------------------------------------------------------------
// Fork-join: zero -> [ place (side stream) || prep -> node (main) ] -> agg.
// ---------------------------------------------------------------------------
extern "C" void kernel_launch(void* const* d_in, const int* in_sizes, int n_in,
                              void* d_out, int out_size) {
    const float* mu = (const float*)d_in[0];
    const float* x  = (const float*)d_in[1];
    const int*   ei = (const int*)d_in[2];
    const float* ew = (const float*)d_in[3];
    const float* W1 = (const float*)d_in[4];
    const float* W2 = (const float*)d_in[5];
    const float* W3 = (const float*)d_in[6];
    const float* W4 = (const float*)d_in[7];

    static cudaStream_t s_side = nullptr;
    static cudaEvent_t ev_fork, ev_join;
    if (!s_side) {
        cudaStreamCreateWithFlags(&s_side, cudaStreamNonBlocking);
        cudaEventCreateWithFlags(&ev_fork, cudaEventDisableTiming);
        cudaEventCreateWithFlags(&ev_join, cudaEventDisableTiming);
    }

    zero_kernel<<<(NNODES + 255) / 256, 256>>>();
    cudaEventRecord(ev_fork, 0);
    cudaStreamWaitEvent(s_side, ev_fork, 0);

    place_kernel<<<(NEDGES + 255) / 256, 256, 0, s_side>>>(ei, ew);

    prep_v_kernel<<<1, 256>>>(W1, W2, W3, W4);
    node_kernel<<<(NNODES + BN - 1) / BN, 256>>>(mu, x, W1);

    cudaEventRecord(ev_join, s_side);
    cudaStreamWaitEvent(0, ev_join, 0);

    agg_final_kernel<<<(NNODES + 15) / 16, 256>>>((float*)d_out);
}